// round 1
// baseline (speedup 1.0000x reference)
#include <cuda_runtime.h>
#include <cstdint>

#define Mdim 8192   // batch
#define Ndim 8192   // hidden
#define Kdim 256    // d_in
#define SAEK 32

// Scratch (allocation-free rule: static __device__ globals)
__device__ float g_pre[(size_t)Mdim * (size_t)Ndim];   // 256 MB pre-activations
__device__ int   g_tk_idx[Mdim * SAEK];
__device__ float g_tk_val[Mdim * SAEK];

// ---------------------------------------------------------------------------
// Kernel 1: fused encoder GEMM: pre = relu((x - b_dec) @ W_enc^T + b_enc)
// ---------------------------------------------------------------------------
#define BM 128
#define BN 128
#define BK 32
#define TM 8
#define TN 8

__global__ __launch_bounds__(256, 2)
void enc_gemm(const float* __restrict__ x, const float* __restrict__ Wenc,
              const float* __restrict__ b_enc, const float* __restrict__ b_dec)
{
    __shared__ float As[BK][BM];   // transposed: [k][m]
    __shared__ float Bs[BK][BN];   // transposed: [k][n]
    __shared__ float s_bdec[Kdim];

    const int tid = threadIdx.x;
    const int m0 = blockIdx.y * BM;
    const int n0 = blockIdx.x * BN;

    s_bdec[tid] = b_dec[tid];      // 256 threads == Kdim
    __syncthreads();

    float acc[TM][TN];
#pragma unroll
    for (int i = 0; i < TM; i++)
#pragma unroll
        for (int j = 0; j < TN; j++) acc[i][j] = 0.f;

    const int ty = tid >> 4;        // 0..15
    const int tx = tid & 15;        // 0..15

    const int lr = tid >> 3;        // 0..31 (row within 32-row load pass)
    const int lc = (tid & 7) * 4;   // k offset 0,4,...,28

    for (int kt = 0; kt < Kdim; kt += BK) {
        // stage tiles (with b_dec fold for A)
#pragma unroll
        for (int i = 0; i < 4; i++) {
            const int row = lr + 32 * i;
            float4 va = *(const float4*)(x + (size_t)(m0 + row) * Kdim + kt + lc);
            va.x -= s_bdec[kt + lc + 0];
            va.y -= s_bdec[kt + lc + 1];
            va.z -= s_bdec[kt + lc + 2];
            va.w -= s_bdec[kt + lc + 3];
            As[lc + 0][row] = va.x;
            As[lc + 1][row] = va.y;
            As[lc + 2][row] = va.z;
            As[lc + 3][row] = va.w;
            float4 vb = *(const float4*)(Wenc + (size_t)(n0 + row) * Kdim + kt + lc);
            Bs[lc + 0][row] = vb.x;
            Bs[lc + 1][row] = vb.y;
            Bs[lc + 2][row] = vb.z;
            Bs[lc + 3][row] = vb.w;
        }
        __syncthreads();

#pragma unroll
        for (int kk = 0; kk < BK; kk++) {
            float a[TM], b[TN];
            *(float4*)&a[0] = *(const float4*)&As[kk][ty * TM + 0];
            *(float4*)&a[4] = *(const float4*)&As[kk][ty * TM + 4];
            *(float4*)&b[0] = *(const float4*)&Bs[kk][tx * TN + 0];
            *(float4*)&b[4] = *(const float4*)&Bs[kk][tx * TN + 4];
#pragma unroll
            for (int i = 0; i < TM; i++)
#pragma unroll
                for (int j = 0; j < TN; j++)
                    acc[i][j] = fmaf(a[i], b[j], acc[i][j]);
        }
        __syncthreads();
    }

    // epilogue: + b_enc, relu, store
    float be[TN];
#pragma unroll
    for (int j = 0; j < TN; j++) be[j] = b_enc[n0 + tx * TN + j];

#pragma unroll
    for (int i = 0; i < TM; i++) {
        const size_t row = (size_t)(m0 + ty * TM + i);
        float* dst = g_pre + row * Ndim + n0 + tx * TN;
        float4 o0, o1;
        o0.x = fmaxf(acc[i][0] + be[0], 0.f);
        o0.y = fmaxf(acc[i][1] + be[1], 0.f);
        o0.z = fmaxf(acc[i][2] + be[2], 0.f);
        o0.w = fmaxf(acc[i][3] + be[3], 0.f);
        o1.x = fmaxf(acc[i][4] + be[4], 0.f);
        o1.y = fmaxf(acc[i][5] + be[5], 0.f);
        o1.z = fmaxf(acc[i][6] + be[6], 0.f);
        o1.w = fmaxf(acc[i][7] + be[7], 0.f);
        ((float4*)dst)[0] = o0;
        ((float4*)dst)[1] = o1;
    }
}

// ---------------------------------------------------------------------------
// Kernel 2: per-row top-32 via float-bit histogram select.
// Values are >= 0 (post-relu), so uint bit pattern is monotonic in value.
// bin = bits >> 20  (2048 bins, 8 per octave).
// ---------------------------------------------------------------------------
#define NBINS 2048
#define CAND_CAP 512

__global__ __launch_bounds__(256)
void topk_kernel()
{
    __shared__ float    s_row[Ndim];        // 32 KB
    __shared__ unsigned s_hist[NBINS];      // 8 KB
    __shared__ int      s_cand[CAND_CAP];   // 2 KB
    __shared__ unsigned s_g[256];
    __shared__ float    s_rv[256];
    __shared__ int      s_ri[256];
    __shared__ int      s_sel_idx[SAEK];
    __shared__ float    s_sel_val[SAEK];
    __shared__ int      s_nsel, s_ncand, s_bstar, s_chi;

    const int row = blockIdx.x;
    const int tid = threadIdx.x;
    const float* pr = g_pre + (size_t)row * Ndim;

    // load row into smem
    for (int i = tid; i < Ndim / 4; i += 256)
        ((float4*)s_row)[i] = ((const float4*)pr)[i];

    int bstar = -1, chi = 0;
    for (int pass = 0; pass < 2; pass++) {
        const unsigned binfloor = (pass == 0) ? 1020u /* bin(1.5) */ : 1u;
        for (int i = tid; i < NBINS; i += 256) s_hist[i] = 0;
        __syncthreads();

        for (int i = tid; i < Ndim; i += 256) {
            unsigned b = __float_as_uint(s_row[i]) >> 20;
            if (b >= binfloor) atomicAdd(&s_hist[b], 1u);
        }
        __syncthreads();

        // group sums (8 bins per thread)
        unsigned gs = 0;
#pragma unroll
        for (int j = 0; j < 8; j++) gs += s_hist[tid * 8 + j];
        s_g[tid] = gs;
        __syncthreads();

        if (tid == 0) {
            unsigned run = 0;
            int fb = -1, fchi = 0;
            for (int g = 255; g >= 0; g--) {
                unsigned nr = run + s_g[g];
                if (nr >= SAEK) {
                    unsigned ca = run;
                    for (int b = g * 8 + 7; b >= g * 8; b--) {
                        unsigned h = s_hist[b];
                        if (ca + h >= SAEK) { fb = b; fchi = (int)ca; break; }
                        ca += h;
                    }
                    break;
                }
                run = nr;
            }
            s_bstar = fb;
            s_chi = (fb >= 0) ? fchi : (int)run;  // if no crossing: total counted
        }
        __syncthreads();
        bstar = s_bstar;
        chi = s_chi;
        if (bstar >= 0) break;
        __syncthreads();
    }
    if (bstar < 0) {        // fewer than K positive values: pad with zeros
        bstar = 0;          // "candidates" = exact zeros (bin 0); chi = total positives
    }

    // collect: bins > bstar -> selected outright; bin == bstar -> candidates
    if (tid == 0) { s_nsel = 0; s_ncand = 0; }
    __syncthreads();
    for (int i = tid; i < Ndim; i += 256) {
        float v = s_row[i];
        int b = (int)(__float_as_uint(v) >> 20);
        if (b > bstar) {
            int p = atomicAdd(&s_nsel, 1);
            s_sel_idx[p] = i;
            s_sel_val[p] = v;
        } else if (b == bstar) {
            int c = atomicAdd(&s_ncand, 1);
            if (c < CAND_CAP) s_cand[c] = i;
        }
    }
    __syncthreads();

    const int m = SAEK - chi;                 // entries to pick from boundary bin
    const int ncand = s_ncand;
    const bool overflow = (ncand > CAND_CAP);
    const int ncl = overflow ? 0 : ncand;

    for (int it = 0; it < m; it++) {
        float bv = -1.0f;
        int bi = 0x7FFFFFFF;
        if (!overflow) {
            for (int j = tid; j < ncl; j += 256) {
                int idx = s_cand[j];
                float v = s_row[idx];
                if (v > bv || (v == bv && idx < bi)) { bv = v; bi = idx; }
            }
        } else {
            for (int i = tid; i < Ndim; i += 256) {
                float v = s_row[i];
                if ((int)(__float_as_uint(v) >> 20) == bstar) {
                    if (v > bv || (v == bv && i < bi)) { bv = v; bi = i; }
                }
            }
        }
        s_rv[tid] = bv; s_ri[tid] = bi;
        __syncthreads();
#pragma unroll
        for (int s = 128; s > 0; s >>= 1) {
            if (tid < s) {
                float ov = s_rv[tid + s]; int oi = s_ri[tid + s];
                if (ov > s_rv[tid] || (ov == s_rv[tid] && oi < s_ri[tid])) {
                    s_rv[tid] = ov; s_ri[tid] = oi;
                }
            }
            __syncthreads();
        }
        if (tid == 0) {
            float fv = s_rv[0]; int fi = s_ri[0];
            if (fv < 0.0f) { fv = 0.0f; fi = 0; }       // degenerate pad
            else s_row[fi] = -2.0f;                      // mark taken
            s_sel_idx[chi + it] = fi;
            s_sel_val[chi + it] = fv;
        }
        __syncthreads();
    }

    if (tid < SAEK) {
        g_tk_idx[row * SAEK + tid] = s_sel_idx[tid];
        g_tk_val[row * SAEK + tid] = s_sel_val[tid];
    }
}

// ---------------------------------------------------------------------------
// Kernel 3: sparse decode: out[b,:] = b_dec + sum_k val_k * W_dec[idx_k,:]
// ---------------------------------------------------------------------------
__global__ __launch_bounds__(256)
void decode_kernel(const float* __restrict__ Wdec, const float* __restrict__ b_dec,
                   float* __restrict__ out)
{
    const int row = blockIdx.x;
    const int d = threadIdx.x;            // 256 == Kdim
    __shared__ int   si[SAEK];
    __shared__ float sv[SAEK];
    if (d < SAEK) {
        si[d] = g_tk_idx[row * SAEK + d];
        sv[d] = g_tk_val[row * SAEK + d];
    }
    __syncthreads();

    float acc = b_dec[d];
#pragma unroll
    for (int j = 0; j < SAEK; j++)
        acc = fmaf(sv[j], __ldg(Wdec + (size_t)si[j] * Kdim + d), acc);
    out[(size_t)row * Kdim + d] = acc;
}

// ---------------------------------------------------------------------------
extern "C" void kernel_launch(void* const* d_in, const int* in_sizes, int n_in,
                              void* d_out, int out_size)
{
    const float* x     = (const float*)d_in[0];
    const float* W_enc = (const float*)d_in[1];
    const float* b_enc = (const float*)d_in[2];
    const float* W_dec = (const float*)d_in[3];
    const float* b_dec = (const float*)d_in[4];
    float* out = (float*)d_out;

    dim3 g1(Ndim / BN, Mdim / BM);
    enc_gemm<<<g1, 256>>>(x, W_enc, b_enc, b_dec);
    topk_kernel<<<Mdim, 256>>>();
    decode_kernel<<<Mdim, 256>>>(W_dec, b_dec, out);
}